// round 1
// baseline (speedup 1.0000x reference)
#include <cuda_runtime.h>

#define BB 4
#define TT 2048
#define DD 1024
#define RR 32

// scratch (no allocations allowed)
__device__ float g_y[BB * TT * RR];   // y = x @ U   [B*T, R]
__device__ float g_n[BB * TT];        // ||y||^2     [B*T]

// ---------------------------------------------------------------------------
// Kernel 1: y = x @ U, n = rowsum(y*y). Block = 64 rows, 256 threads.
// ---------------------------------------------------------------------------
__global__ __launch_bounds__(256) void yn_kernel(const float* __restrict__ x,
                                                 const float* __restrict__ U) {
    __shared__ float sX[64 * 32];   // 8 KB
    __shared__ float sU[32 * 32];   // 4 KB

    const int tid  = threadIdx.x;
    const int w    = tid >> 5;
    const int lane = tid & 31;
    const int row0 = blockIdx.x * 64;

    float acc[8];
#pragma unroll
    for (int k = 0; k < 8; k++) acc[k] = 0.f;

    for (int d0 = 0; d0 < DD; d0 += 32) {
        __syncthreads();
#pragma unroll
        for (int idx = tid; idx < 64 * 32; idx += 256) {
            int r_ = idx >> 5, dd = idx & 31;
            sX[idx] = x[(size_t)(row0 + r_) * DD + d0 + dd];
        }
#pragma unroll
        for (int idx = tid; idx < 32 * 32; idx += 256) {
            sU[idx] = U[(size_t)(d0 + (idx >> 5)) * RR + (idx & 31)];
        }
        __syncthreads();

#pragma unroll
        for (int dd4 = 0; dd4 < 8; dd4++) {
            float u0 = sU[(dd4 * 4 + 0) * 32 + lane];
            float u1 = sU[(dd4 * 4 + 1) * 32 + lane];
            float u2 = sU[(dd4 * 4 + 2) * 32 + lane];
            float u3 = sU[(dd4 * 4 + 3) * 32 + lane];
#pragma unroll
            for (int k = 0; k < 8; k++) {
                const float4 xv = *(const float4*)&sX[(w * 8 + k) * 32 + dd4 * 4];
                acc[k] = fmaf(xv.x, u0, acc[k]);
                acc[k] = fmaf(xv.y, u1, acc[k]);
                acc[k] = fmaf(xv.z, u2, acc[k]);
                acc[k] = fmaf(xv.w, u3, acc[k]);
            }
        }
    }

#pragma unroll
    for (int k = 0; k < 8; k++) {
        int rg = row0 + w * 8 + k;
        g_y[(size_t)rg * RR + lane] = acc[k];
        float v = acc[k] * acc[k];
#pragma unroll
        for (int off = 16; off; off >>= 1)
            v += __shfl_xor_sync(0xffffffffu, v, off);
        if (lane == 0) g_n[rg] = v;
    }
}

// ---------------------------------------------------------------------------
// Kernel 2: flash attention. Block handles (b, 32 query rows, 128 d-cols).
// 256 threads / 8 warps; warp owns 4 rows; lane owns 4 contiguous d-cols.
// ---------------------------------------------------------------------------
#define BM 32
#define BN 32
#define DC 128
#define L2E 1.4426950408889634f

__global__ __launch_bounds__(256) void flash_kernel(const float* __restrict__ x,
                                                    float* __restrict__ out) {
    __shared__ float sYj[BN * 33];      // [key j][r], pad 33 -> conflict-free
    __shared__ float sYiT[RR * BM];     // [r][query i] for float4 broadcast
    __shared__ float sN[BN];
    __shared__ float sX[BN * DC];       // 16 KB value tile
    __shared__ float sP[BM * BN];       // softmax probs, row = warp*4+i

    const int tid  = threadIdx.x;
    const int w    = tid >> 5;
    const int lane = tid & 31;
    const int b    = blockIdx.z;
    const int i0   = blockIdx.y * BM;
    const int dc0  = blockIdx.x * DC;

    // query y tile, transposed
    for (int idx = tid; idx < BM * RR; idx += 256) {
        int i = idx >> 5, r = idx & 31;
        sYiT[r * BM + i] = g_y[(size_t)(b * TT + i0 + i) * RR + r];
    }

    float acc[4][4];
#pragma unroll
    for (int i = 0; i < 4; i++)
#pragma unroll
        for (int c = 0; c < 4; c++) acc[i][c] = 0.f;
    float m[4] = {-1e30f, -1e30f, -1e30f, -1e30f};
    float l[4] = {0.f, 0.f, 0.f, 0.f};

    const float* xb = x + (size_t)b * TT * DD;

    for (int j0 = 0; j0 < TT; j0 += BN) {
        __syncthreads();
        for (int idx = tid; idx < BN * RR; idx += 256) {
            int j = idx >> 5, r = idx & 31;
            sYj[j * 33 + r] = g_y[(size_t)(b * TT + j0 + j) * RR + r];
        }
        if (tid < BN) sN[tid] = g_n[b * TT + j0 + tid];
        for (int idx = tid; idx < BN * DC / 4; idx += 256) {
            int j = idx / (DC / 4), c4 = idx % (DC / 4);
            *(float4*)&sX[j * DC + c4 * 4] =
                *(const float4*)&xb[(size_t)(j0 + j) * DD + dc0 + c4 * 4];
        }
        __syncthreads();

        // ---- scores: lane = key j, 4 query rows per warp ----
        float s0 = 0.f, s1 = 0.f, s2 = 0.f, s3 = 0.f;
#pragma unroll
        for (int r = 0; r < RR; r++) {
            float  yj = sYj[lane * 33 + r];
            float4 yi = *(const float4*)&sYiT[r * BM + w * 4];
            s0 = fmaf(yi.x, yj, s0);
            s1 = fmaf(yi.y, yj, s1);
            s2 = fmaf(yi.z, yj, s2);
            s3 = fmaf(yi.w, yj, s3);
        }
        const float nj = sN[lane];
        float s[4] = {2.f * s0 - nj, 2.f * s1 - nj, 2.f * s2 - nj, 2.f * s3 - nj};

        // ---- online softmax ----
#pragma unroll
        for (int i = 0; i < 4; i++) {
            float tmax = s[i];
#pragma unroll
            for (int off = 16; off; off >>= 1)
                tmax = fmaxf(tmax, __shfl_xor_sync(0xffffffffu, tmax, off));
            float nm    = fmaxf(m[i], tmax);
            float alpha = exp2f((m[i] - nm) * L2E);
            float p     = exp2f((s[i] - nm) * L2E);
            float ps    = p;
#pragma unroll
            for (int off = 16; off; off >>= 1)
                ps += __shfl_xor_sync(0xffffffffu, ps, off);
            l[i] = l[i] * alpha + ps;
            m[i] = nm;
#pragma unroll
            for (int c = 0; c < 4; c++) acc[i][c] *= alpha;
            sP[(w * 4 + i) * BN + lane] = p;
        }
        __syncwarp();

        // ---- PV: acc[i][c] += sum_j P[i][j] * x[j][c] ----
#pragma unroll
        for (int j4 = 0; j4 < BN / 4; j4++) {
            const float4 xv0 = *(const float4*)&sX[(j4 * 4 + 0) * DC + lane * 4];
            const float4 xv1 = *(const float4*)&sX[(j4 * 4 + 1) * DC + lane * 4];
            const float4 xv2 = *(const float4*)&sX[(j4 * 4 + 2) * DC + lane * 4];
            const float4 xv3 = *(const float4*)&sX[(j4 * 4 + 3) * DC + lane * 4];
#pragma unroll
            for (int i = 0; i < 4; i++) {
                const float4 p4 = *(const float4*)&sP[(w * 4 + i) * BN + j4 * 4];
                acc[i][0] = fmaf(p4.x, xv0.x, acc[i][0]);
                acc[i][0] = fmaf(p4.y, xv1.x, acc[i][0]);
                acc[i][0] = fmaf(p4.z, xv2.x, acc[i][0]);
                acc[i][0] = fmaf(p4.w, xv3.x, acc[i][0]);
                acc[i][1] = fmaf(p4.x, xv0.y, acc[i][1]);
                acc[i][1] = fmaf(p4.y, xv1.y, acc[i][1]);
                acc[i][1] = fmaf(p4.z, xv2.y, acc[i][1]);
                acc[i][1] = fmaf(p4.w, xv3.y, acc[i][1]);
                acc[i][2] = fmaf(p4.x, xv0.z, acc[i][2]);
                acc[i][2] = fmaf(p4.y, xv1.z, acc[i][2]);
                acc[i][2] = fmaf(p4.z, xv2.z, acc[i][2]);
                acc[i][2] = fmaf(p4.w, xv3.z, acc[i][2]);
                acc[i][3] = fmaf(p4.x, xv0.w, acc[i][3]);
                acc[i][3] = fmaf(p4.y, xv1.w, acc[i][3]);
                acc[i][3] = fmaf(p4.z, xv2.w, acc[i][3]);
                acc[i][3] = fmaf(p4.w, xv3.w, acc[i][3]);
            }
        }
    }

    // epilogue
#pragma unroll
    for (int i = 0; i < 4; i++) {
        float inv = 1.0f / l[i];
        float4 o;
        o.x = acc[i][0] * inv;
        o.y = acc[i][1] * inv;
        o.z = acc[i][2] * inv;
        o.w = acc[i][3] * inv;
        *(float4*)&out[(size_t)(b * TT + i0 + w * 4 + i) * DD + dc0 + lane * 4] = o;
    }
}

extern "C" void kernel_launch(void* const* d_in, const int* in_sizes, int n_in,
                              void* d_out, int out_size) {
    const float* x = (const float*)d_in[0];   // [B,T,D] fp32
    const float* U = (const float*)d_in[1];   // [D,R]   fp32
    float* out = (float*)d_out;

    yn_kernel<<<(BB * TT) / 64, 256>>>(x, U);
    dim3 grid(DD / DC, TT / BM, BB);
    flash_kernel<<<grid, 256>>>(x, out);
}

// round 4
// speedup vs baseline: 4.5735x; 4.5735x over previous
#include <cuda_runtime.h>

typedef unsigned int u32;

#define BB 4
#define TT 2048
#define DD 1024
#define RR 32

#define BM 128
#define BN 32
#define DC 256
#define NT (TT / BN)

// scratch (no allocations allowed)
__device__ float g_y[BB * TT * RR];   // y = x @ U   [B*T, R]
__device__ float g_n[BB * TT];        // ||y||^2

// ---------------------------------------------------------------------------
// Kernel 1: y = x @ U, n = rowsum(y*y). (known correct from R1)
// ---------------------------------------------------------------------------
__global__ __launch_bounds__(256) void yn_kernel(const float* __restrict__ x,
                                                 const float* __restrict__ U) {
    __shared__ float sX[64 * 32];
    __shared__ float sU[32 * 32];

    const int tid  = threadIdx.x;
    const int w    = tid >> 5;
    const int lane = tid & 31;
    const int row0 = blockIdx.x * 64;

    float acc[8];
#pragma unroll
    for (int k = 0; k < 8; k++) acc[k] = 0.f;

    for (int d0 = 0; d0 < DD; d0 += 32) {
        __syncthreads();
        for (int idx = tid; idx < 64 * 32; idx += 256) {
            int r_ = idx >> 5, dd = idx & 31;
            sX[idx] = x[(size_t)(row0 + r_) * DD + d0 + dd];
        }
        for (int idx = tid; idx < 32 * 32; idx += 256) {
            sU[idx] = U[(size_t)(d0 + (idx >> 5)) * RR + (idx & 31)];
        }
        __syncthreads();

#pragma unroll
        for (int dd4 = 0; dd4 < 8; dd4++) {
            float u0 = sU[(dd4 * 4 + 0) * 32 + lane];
            float u1 = sU[(dd4 * 4 + 1) * 32 + lane];
            float u2 = sU[(dd4 * 4 + 2) * 32 + lane];
            float u3 = sU[(dd4 * 4 + 3) * 32 + lane];
#pragma unroll
            for (int k = 0; k < 8; k++) {
                const float4 xv = *(const float4*)&sX[(w * 8 + k) * 32 + dd4 * 4];
                acc[k] = fmaf(xv.x, u0, acc[k]);
                acc[k] = fmaf(xv.y, u1, acc[k]);
                acc[k] = fmaf(xv.z, u2, acc[k]);
                acc[k] = fmaf(xv.w, u3, acc[k]);
            }
        }
    }

#pragma unroll
    for (int k = 0; k < 8; k++) {
        int rg = row0 + w * 8 + k;
        g_y[(size_t)rg * RR + lane] = acc[k];
        float v = acc[k] * acc[k];
#pragma unroll
        for (int off = 16; off; off >>= 1)
            v += __shfl_xor_sync(0xffffffffu, v, off);
        if (lane == 0) g_n[rg] = v;
    }
}

// ---------------------------------------------------------------------------
// Kernel 2: flash attention via mma.sync tf32 (static max = n_i, no rescale)
// ---------------------------------------------------------------------------

// smem float-index layout
#define YI_F 0                         // [128][36]
#define P_F  4608                      // [128][36]
#define YJ_F(q) (9216 + (q) * 1152)    // [32][36] x2
#define NJ_F(q) (11520 + (q) * 32)     // [32] x2
#define L_F  11584                     // [2][128]
#define X_F(q) (11840 + (q) * 8448)    // [32][264] x2
#define SMEM_FLOATS (11840 + 2 * 8448)
#define SMEM_TOTAL (SMEM_FLOATS * 4)   // 114944 B

#define YSTR 36
#define XSTR 264

__device__ __forceinline__ u32 s2u(const void* p) {
    u32 a;
    asm("{ .reg .u64 t; cvta.to.shared.u64 t, %1; cvt.u32.u64 %0, t; }" : "=r"(a) : "l"(p));
    return a;
}

__device__ __forceinline__ void cp16(u32 dst, const void* src) {
    asm volatile("cp.async.cg.shared.global [%0], [%1], 16;" :: "r"(dst), "l"(src));
}

__device__ __forceinline__ void mma8(float* d, const u32* a, u32 b0, u32 b1,
                                     const float* c) {
    asm volatile(
        "mma.sync.aligned.m16n8k8.row.col.f32.tf32.tf32.f32 "
        "{%0,%1,%2,%3}, {%4,%5,%6,%7}, {%8,%9}, {%10,%11,%12,%13};"
        : "=f"(d[0]), "=f"(d[1]), "=f"(d[2]), "=f"(d[3])
        : "r"(a[0]), "r"(a[1]), "r"(a[2]), "r"(a[3]), "r"(b0), "r"(b1),
          "f"(c[0]), "f"(c[1]), "f"(c[2]), "f"(c[3]));
}

__device__ __forceinline__ u32 fu(float v) { return __float_as_uint(v); }

__global__ __launch_bounds__(512, 1) void flash_kernel(const float* __restrict__ x,
                                                       float* __restrict__ out) {
    extern __shared__ float s[];
    const u32 su = s2u(s);

    const int tid  = threadIdx.x;
    const int w    = tid >> 5;
    const int lane = tid & 31;
    const int wm   = w >> 1;        // 0..7  (16 query rows each)
    const int wn   = w & 1;         // 0..1  (n-halves)
    const int lq   = lane >> 2;     // 0..7
    const int lr   = lane & 3;      // 0..3

    const int b   = blockIdx.z;
    const int i0  = blockIdx.y * BM;
    const int dc0 = blockIdx.x * DC;
    const int bTT = b * TT;

    // ---- prologue: Yi + tile 0 (group G0) ----
    for (int idx = tid; idx < 1024; idx += 512) {          // Yi: 128 rows x 8 chunks
        int r_ = idx >> 3, u = idx & 7;
        cp16(su + (YI_F + r_ * YSTR) * 4 + u * 16,
             g_y + (size_t)(bTT + i0 + r_) * RR + u * 4);
    }
    for (int idx = tid; idx < 2048; idx += 512) {          // X tile 0: 32 x 64 chunks
        int r_ = idx >> 6, u = idx & 63;
        cp16(su + X_F(0) * 4 + r_ * (XSTR * 4) + u * 16,
             x + (size_t)(bTT + r_) * DD + dc0 + u * 4);
    }
    if (tid < 256) {                                       // Yj tile 0
        int r_ = tid >> 3, u = tid & 7;
        cp16(su + (YJ_F(0) + r_ * YSTR) * 4 + u * 16,
             g_y + (size_t)(bTT + r_) * RR + u * 4);
    }
    if (tid < 8)
        cp16(su + NJ_F(0) * 4 + tid * 16, g_n + bTT + tid * 4);
    asm volatile("cp.async.commit_group;" ::: "memory");

    const float ni0 = g_n[bTT + i0 + wm * 16 + lq];
    const float ni1 = g_n[bTT + i0 + wm * 16 + lq + 8];

    float acc[16][4];
#pragma unroll
    for (int nt = 0; nt < 16; nt++)
#pragma unroll
        for (int c = 0; c < 4; c++) acc[nt][c] = 0.f;
    float l0 = 0.f, l1 = 0.f;

    u32 aY[4][4];   // Yi A-fragments (loop-invariant), loaded at t==0

    for (int t = 0; t < NT; t++) {
        const int q = t & 1;

        __syncthreads();   // (a) prior iter's reads of buffers[1-q] + sP done

        if (t + 1 < NT) {  // prefetch tile t+1 into 1-q
            const int j0n = (t + 1) * BN;
            for (int idx = tid; idx < 2048; idx += 512) {
                int r_ = idx >> 6, u = idx & 63;
                cp16(su + X_F(1 - q) * 4 + r_ * (XSTR * 4) + u * 16,
                     x + (size_t)(bTT + j0n + r_) * DD + dc0 + u * 4);
            }
            if (tid < 256) {
                int r_ = tid >> 3, u = tid & 7;
                cp16(su + (YJ_F(1 - q) + r_ * YSTR) * 4 + u * 16,
                     g_y + (size_t)(bTT + j0n + r_) * RR + u * 4);
            }
            if (tid < 8)
                cp16(su + NJ_F(1 - q) * 4 + tid * 16, g_n + bTT + j0n + tid * 4);
            asm volatile("cp.async.commit_group;" ::: "memory");
            asm volatile("cp.async.wait_group 1;" ::: "memory");
        } else {
            asm volatile("cp.async.wait_group 0;" ::: "memory");
        }
        __syncthreads();   // (b) group t visible block-wide

        if (t == 0) {      // preload Yi A-frags
#pragma unroll
            for (int kt = 0; kt < 4; kt++) {
                int base = YI_F + (wm * 16 + lq) * YSTR + kt * 8 + lr;
                aY[kt][0] = fu(s[base]);
                aY[kt][1] = fu(s[base + 8 * YSTR]);
                aY[kt][2] = fu(s[base + 4]);
                aY[kt][3] = fu(s[base + 8 * YSTR + 4]);
            }
        }

        // ---- MMA1: S[128x32]; warp tile 16m x 16n ----
        const int yjb = YJ_F(q) + (wn * 16 + lq) * YSTR + lr;
        float S[2][4];
#pragma unroll
        for (int nt = 0; nt < 2; nt++) {
#pragma unroll
            for (int c = 0; c < 4; c++) S[nt][c] = 0.f;
#pragma unroll
            for (int kt = 0; kt < 4; kt++) {
                u32 b0 = fu(s[yjb + nt * 8 * YSTR + kt * 8]);
                u32 b1 = fu(s[yjb + nt * 8 * YSTR + kt * 8 + 4]);
                mma8(S[nt], aY[kt], b0, b1, S[nt]);
            }
        }

        // ---- softmax: p = exp(2S - ni - nj); store to sP ----
        const int pb = P_F + (wm * 16 + lq) * YSTR + wn * 16 + lr * 2;
#pragma unroll
        for (int nt = 0; nt < 2; nt++) {
            float2 nj = *(const float2*)&s[NJ_F(q) + wn * 16 + nt * 8 + lr * 2];
            float p0 = __expf(fmaf(S[nt][0], 2.f, -ni0 - nj.x));
            float p1 = __expf(fmaf(S[nt][1], 2.f, -ni0 - nj.y));
            float p2 = __expf(fmaf(S[nt][2], 2.f, -ni1 - nj.x));
            float p3 = __expf(fmaf(S[nt][3], 2.f, -ni1 - nj.y));
            l0 += p0 + p1;
            l1 += p2 + p3;
            *(float2*)&s[pb + nt * 8]            = make_float2(p0, p1);
            *(float2*)&s[pb + nt * 8 + 8 * YSTR] = make_float2(p2, p3);
        }
        __syncthreads();   // (c) sP visible

        // ---- MMA2: acc[128x256] += P[128x32] @ X[32x256]; warp 16m x 128n ----
        u32 aP[4][4];
        const int pab = P_F + (wm * 16 + lq) * YSTR + lr;
#pragma unroll
        for (int kt = 0; kt < 4; kt++) {
            aP[kt][0] = fu(s[pab + kt * 8]);
            aP[kt][1] = fu(s[pab + kt * 8 + 8 * YSTR]);
            aP[kt][2] = fu(s[pab + kt * 8 + 4]);
            aP[kt][3] = fu(s[pab + kt * 8 + 8 * YSTR + 4]);
        }
        const int xb = X_F(q) + lr * XSTR + wn * 128 + lq;
#pragma unroll
        for (int nt = 0; nt < 16; nt++) {
#pragma unroll
            for (int kt = 0; kt < 4; kt++) {
                u32 b0 = fu(s[xb + kt * 8 * XSTR + nt * 8]);
                u32 b1 = fu(s[xb + (kt * 8 + 4) * XSTR + nt * 8]);
                mma8(acc[nt], aP[kt], b0, b1, acc[nt]);
            }
        }
    }

    // ---- epilogue: row sums across quad + wn halves, then normalize ----
    l0 += __shfl_xor_sync(0xffffffffu, l0, 1);
    l0 += __shfl_xor_sync(0xffffffffu, l0, 2);
    l1 += __shfl_xor_sync(0xffffffffu, l1, 1);
    l1 += __shfl_xor_sync(0xffffffffu, l1, 2);
    if (lr == 0) {
        s[L_F + wn * 128 + wm * 16 + lq]     = l0;
        s[L_F + wn * 128 + wm * 16 + lq + 8] = l1;
    }
    __syncthreads();

    const int r0 = wm * 16 + lq;
    const float inv0 = 1.0f / (s[L_F + r0] + s[L_F + 128 + r0]);
    const float inv1 = 1.0f / (s[L_F + r0 + 8] + s[L_F + 128 + r0 + 8]);

    float* o0 = out + (size_t)(bTT + i0 + r0) * DD + dc0 + wn * 128 + lr * 2;
    float* o1 = o0 + 8 * DD;
#pragma unroll
    for (int nt = 0; nt < 16; nt++) {
        *(float2*)(o0 + nt * 8) = make_float2(acc[nt][0] * inv0, acc[nt][1] * inv0);
        *(float2*)(o1 + nt * 8) = make_float2(acc[nt][2] * inv1, acc[nt][3] * inv1);
    }
}

extern "C" void kernel_launch(void* const* d_in, const int* in_sizes, int n_in,
                              void* d_out, int out_size) {
    const float* x = (const float*)d_in[0];   // [B,T,D] fp32
    const float* U = (const float*)d_in[1];   // [D,R]   fp32
    float* out = (float*)d_out;

    yn_kernel<<<(BB * TT) / 64, 256>>>(x, U);

    cudaFuncSetAttribute(flash_kernel, cudaFuncAttributeMaxDynamicSharedMemorySize,
                         SMEM_TOTAL);
    dim3 grid(DD / DC, TT / BM, BB);
    flash_kernel<<<grid, 512, SMEM_TOTAL>>>(x, out);
}

// round 5
// speedup vs baseline: 4.9927x; 1.0917x over previous
#include <cuda_runtime.h>

typedef unsigned int u32;

#define BB 4
#define TT 2048
#define DD 1024
#define RR 32

#define BM 128
#define BN 32
#define DC 256
#define NT (TT / BN)

// scratch (no allocations allowed)
__device__ float g_y[BB * TT * RR];   // y = x @ U   [B*T, R]
__device__ float g_n[BB * TT];        // ||y||^2

__device__ __forceinline__ u32 s2u(const void* p) {
    u32 a;
    asm("{ .reg .u64 t; cvta.to.shared.u64 t, %1; cvt.u32.u64 %0, t; }" : "=r"(a) : "l"(p));
    return a;
}
__device__ __forceinline__ void cp16(u32 dst, const void* src) {
    asm volatile("cp.async.cg.shared.global [%0], [%1], 16;" :: "r"(dst), "l"(src));
}
__device__ __forceinline__ u32 fu(float v) { return __float_as_uint(v); }
__device__ __forceinline__ u32 tf32r(float v) {
    u32 r;
    asm("cvt.rna.tf32.f32 %0, %1;" : "=r"(r) : "f"(v));
    return r;
}

// ---------------------------------------------------------------------------
// Kernel 1: y = x @ U, n = rowsum(y*y). Double-buffered 128-d chunks.
// Block: 256 threads / 8 warps, 64 rows. Grid: 128.
// ---------------------------------------------------------------------------
#define K1_XF(q) ((q) * 8192)            // [64][128] floats
#define K1_UF(q) (16384 + (q) * 4608)    // [128][36] floats
#define K1_SMEM ((16384 + 2 * 4608) * 4) // 102400 B

__global__ __launch_bounds__(256, 1) void yn_kernel(const float* __restrict__ x,
                                                    const float* __restrict__ U) {
    extern __shared__ float s[];
    const u32 su = s2u(s);

    const int tid  = threadIdx.x;
    const int w    = tid >> 5;
    const int lane = tid & 31;
    const int row0 = blockIdx.x * 64;

    // prologue: chunk 0
    for (int idx = tid; idx < 2048; idx += 256) {
        int r_ = idx >> 5, u = idx & 31;
        cp16(su + K1_XF(0) * 4 + (r_ * 128 + u * 4) * 4,
             x + (size_t)(row0 + r_) * DD + u * 4);
    }
    for (int idx = tid; idx < 1024; idx += 256) {
        int d = idx >> 3, u = idx & 7;
        cp16(su + K1_UF(0) * 4 + (d * 36 + u * 4) * 4,
             U + (size_t)d * RR + u * 4);
    }
    asm volatile("cp.async.commit_group;" ::: "memory");

    float acc[8];
#pragma unroll
    for (int k = 0; k < 8; k++) acc[k] = 0.f;

    for (int c = 0; c < 8; c++) {
        const int q = c & 1;
        asm volatile("cp.async.wait_group 0;" ::: "memory");
        __syncthreads();

        if (c + 1 < 8) {
            const int d0n = (c + 1) * 128;
            for (int idx = tid; idx < 2048; idx += 256) {
                int r_ = idx >> 5, u = idx & 31;
                cp16(su + K1_XF(1 - q) * 4 + (r_ * 128 + u * 4) * 4,
                     x + (size_t)(row0 + r_) * DD + d0n + u * 4);
            }
            for (int idx = tid; idx < 1024; idx += 256) {
                int d = idx >> 3, u = idx & 7;
                cp16(su + K1_UF(1 - q) * 4 + ((d * 36 + u * 4)) * 4,
                     U + (size_t)(d0n + d) * RR + u * 4);
            }
            asm volatile("cp.async.commit_group;" ::: "memory");
        }

        const float* sX = s + K1_XF(q);
        const float* sU = s + K1_UF(q);
#pragma unroll
        for (int dd4 = 0; dd4 < 32; dd4++) {
            float u0 = sU[(dd4 * 4 + 0) * 36 + lane];
            float u1 = sU[(dd4 * 4 + 1) * 36 + lane];
            float u2 = sU[(dd4 * 4 + 2) * 36 + lane];
            float u3 = sU[(dd4 * 4 + 3) * 36 + lane];
#pragma unroll
            for (int k = 0; k < 8; k++) {
                const float4 xv = *(const float4*)&sX[(w * 8 + k) * 128 + dd4 * 4];
                acc[k] = fmaf(xv.x, u0, acc[k]);
                acc[k] = fmaf(xv.y, u1, acc[k]);
                acc[k] = fmaf(xv.z, u2, acc[k]);
                acc[k] = fmaf(xv.w, u3, acc[k]);
            }
        }
    }

#pragma unroll
    for (int k = 0; k < 8; k++) {
        int rg = row0 + w * 8 + k;
        g_y[(size_t)rg * RR + lane] = acc[k];
        float v = acc[k] * acc[k];
#pragma unroll
        for (int off = 16; off; off >>= 1)
            v += __shfl_xor_sync(0xffffffffu, v, off);
        if (lane == 0) g_n[rg] = v;
    }
}

// ---------------------------------------------------------------------------
// Kernel 2: flash attention via mma.sync tf32 (static max = n_i, no rescale)
// 16 warps as 4 wm x 4 wn; warp tile: 32m x 64n.
// ---------------------------------------------------------------------------
#define YI_F 0                         // [128][36]
#define P_F  4608                      // [128][36]
#define YJ_F(q) (9216 + (q) * 1152)    // [32][36] x2
#define NJ_F(q) (11520 + (q) * 32)     // [32] x2
#define L_F  0                         // [4][128]  (reuses YI in epilogue)
#define X_F(q) (11840 + (q) * 8448)    // [32][264] x2
#define SMEM_TOTAL ((11840 + 2 * 8448) * 4)

#define YSTR 36
#define XSTR 264

__device__ __forceinline__ void mma8(float* d, const u32* a, u32 b0, u32 b1,
                                     const float* c) {
    asm volatile(
        "mma.sync.aligned.m16n8k8.row.col.f32.tf32.tf32.f32 "
        "{%0,%1,%2,%3}, {%4,%5,%6,%7}, {%8,%9}, {%10,%11,%12,%13};"
        : "=f"(d[0]), "=f"(d[1]), "=f"(d[2]), "=f"(d[3])
        : "r"(a[0]), "r"(a[1]), "r"(a[2]), "r"(a[3]), "r"(b0), "r"(b1),
          "f"(c[0]), "f"(c[1]), "f"(c[2]), "f"(c[3]));
}

__global__ __launch_bounds__(512, 1) void flash_kernel(const float* __restrict__ x,
                                                       float* __restrict__ out) {
    extern __shared__ float s[];
    const u32 su = s2u(s);

    const int tid  = threadIdx.x;
    const int w    = tid >> 5;
    const int lane = tid & 31;
    const int wm   = w >> 2;        // 0..3 : 32 query rows each
    const int wn   = w & 3;         // 0..3 : 64 d-cols (MMA2) / 8 s-cols (MMA1)
    const int lq   = lane >> 2;     // 0..7
    const int lr   = lane & 3;      // 0..3

    const int b   = blockIdx.z;
    const int i0  = blockIdx.y * BM;
    const int dc0 = blockIdx.x * DC;
    const int bTT = b * TT;

    // ---- prologue: Yi + tile 0 ----
    for (int idx = tid; idx < 1024; idx += 512) {
        int r_ = idx >> 3, u = idx & 7;
        cp16(su + (YI_F + r_ * YSTR) * 4 + u * 16,
             g_y + (size_t)(bTT + i0 + r_) * RR + u * 4);
    }
    for (int idx = tid; idx < 2048; idx += 512) {
        int r_ = idx >> 6, u = idx & 63;
        cp16(su + X_F(0) * 4 + r_ * (XSTR * 4) + u * 16,
             x + (size_t)(bTT + r_) * DD + dc0 + u * 4);
    }
    if (tid < 256) {
        int r_ = tid >> 3, u = tid & 7;
        cp16(su + (YJ_F(0) + r_ * YSTR) * 4 + u * 16,
             g_y + (size_t)(bTT + r_) * RR + u * 4);
    }
    if (tid < 8)
        cp16(su + NJ_F(0) * 4 + tid * 16, g_n + bTT + tid * 4);
    asm volatile("cp.async.commit_group;" ::: "memory");

    float ni[2][2];
#pragma unroll
    for (int mt = 0; mt < 2; mt++) {
        ni[mt][0] = g_n[bTT + i0 + wm * 32 + mt * 16 + lq];
        ni[mt][1] = g_n[bTT + i0 + wm * 32 + mt * 16 + lq + 8];
    }

    float acc[2][8][4];
#pragma unroll
    for (int mt = 0; mt < 2; mt++)
#pragma unroll
        for (int nt = 0; nt < 8; nt++)
#pragma unroll
            for (int c = 0; c < 4; c++) acc[mt][nt][c] = 0.f;
    float lsum[2][2] = {{0.f, 0.f}, {0.f, 0.f}};

    for (int t = 0; t < NT; t++) {
        const int q = t & 1;

        asm volatile("cp.async.wait_group 0;" ::: "memory");
        __syncthreads();   // tile t visible; prior readers of buf 1-q done

        if (t + 1 < NT) {  // prefetch t+1 into buf 1-q (safe after the sync)
            const int j0n = (t + 1) * BN;
            for (int idx = tid; idx < 2048; idx += 512) {
                int r_ = idx >> 6, u = idx & 63;
                cp16(su + X_F(1 - q) * 4 + r_ * (XSTR * 4) + u * 16,
                     x + (size_t)(bTT + j0n + r_) * DD + dc0 + u * 4);
            }
            if (tid < 256) {
                int r_ = tid >> 3, u = tid & 7;
                cp16(su + (YJ_F(1 - q) + r_ * YSTR) * 4 + u * 16,
                     g_y + (size_t)(bTT + j0n + r_) * RR + u * 4);
            }
            if (tid < 8)
                cp16(su + NJ_F(1 - q) * 4 + tid * 16, g_n + bTT + j0n + tid * 4);
            asm volatile("cp.async.commit_group;" ::: "memory");
        }

        // ---- MMA1: S[32m x 8n] per warp (m: 32*wm, n: 8*wn) ----
        float S[2][4];
        {
            u32 aY[4];
            const int yjb = YJ_F(q) + (wn * 8 + lq) * YSTR + lr;
#pragma unroll
            for (int mt = 0; mt < 2; mt++) {
#pragma unroll
                for (int c = 0; c < 4; c++) S[mt][c] = 0.f;
            }
#pragma unroll
            for (int kt = 0; kt < 4; kt++) {
                u32 b0 = fu(s[yjb + kt * 8]);
                u32 b1 = fu(s[yjb + kt * 8 + 4]);
#pragma unroll
                for (int mt = 0; mt < 2; mt++) {
                    const int yib = YI_F + (wm * 32 + mt * 16 + lq) * YSTR + kt * 8 + lr;
                    aY[0] = fu(s[yib]);
                    aY[1] = fu(s[yib + 8 * YSTR]);
                    aY[2] = fu(s[yib + 4]);
                    aY[3] = fu(s[yib + 8 * YSTR + 4]);
                    mma8(S[mt], aY, b0, b1, S[mt]);
                }
            }
        }

        // ---- softmax: p = exp(2S - ni - nj); store to sP ----
        {
            const float2 nj = *(const float2*)&s[NJ_F(q) + wn * 8 + lr * 2];
#pragma unroll
            for (int mt = 0; mt < 2; mt++) {
                float p0 = __expf(fmaf(S[mt][0], 2.f, -ni[mt][0] - nj.x));
                float p1 = __expf(fmaf(S[mt][1], 2.f, -ni[mt][0] - nj.y));
                float p2 = __expf(fmaf(S[mt][2], 2.f, -ni[mt][1] - nj.x));
                float p3 = __expf(fmaf(S[mt][3], 2.f, -ni[mt][1] - nj.y));
                lsum[mt][0] += p0 + p1;
                lsum[mt][1] += p2 + p3;
                const int pb = P_F + (wm * 32 + mt * 16 + lq) * YSTR + wn * 8 + lr * 2;
                *(float2*)&s[pb]            = make_float2(p0, p1);
                *(float2*)&s[pb + 8 * YSTR] = make_float2(p2, p3);
            }
        }
        __syncthreads();   // sP visible

        // ---- MMA2: acc[32m x 64n] += P[32m x 32k] @ X[32k x 64n] ----
        u32 aP[2][4][4];
#pragma unroll
        for (int mt = 0; mt < 2; mt++) {
            const int pab = P_F + (wm * 32 + mt * 16 + lq) * YSTR + lr;
#pragma unroll
            for (int kt = 0; kt < 4; kt++) {
                aP[mt][kt][0] = fu(s[pab + kt * 8]);
                aP[mt][kt][1] = fu(s[pab + kt * 8 + 8 * YSTR]);
                aP[mt][kt][2] = fu(s[pab + kt * 8 + 4]);
                aP[mt][kt][3] = fu(s[pab + kt * 8 + 8 * YSTR + 4]);
            }
        }
        const int xb = X_F(q) + lr * XSTR + wn * 64 + lq;
#pragma unroll
        for (int nt = 0; nt < 8; nt++) {
#pragma unroll
            for (int kt = 0; kt < 4; kt++) {
                u32 b0 = tf32r(s[xb + kt * 8 * XSTR + nt * 8]);
                u32 b1 = tf32r(s[xb + (kt * 8 + 4) * XSTR + nt * 8]);
                mma8(acc[0][nt], aP[0][kt], b0, b1, acc[0][nt]);
                mma8(acc[1][nt], aP[1][kt], b0, b1, acc[1][nt]);
            }
        }
    }

    // ---- epilogue: reduce l across quad + 4 wn groups, normalize, store ----
    __syncthreads();   // done with Yi region; reuse as L
#pragma unroll
    for (int mt = 0; mt < 2; mt++)
#pragma unroll
        for (int h = 0; h < 2; h++) {
            float v = lsum[mt][h];
            v += __shfl_xor_sync(0xffffffffu, v, 1);
            v += __shfl_xor_sync(0xffffffffu, v, 2);
            if (lr == 0)
                s[L_F + wn * 128 + wm * 32 + mt * 16 + lq + 8 * h] = v;
        }
    __syncthreads();

#pragma unroll
    for (int mt = 0; mt < 2; mt++) {
#pragma unroll
        for (int h = 0; h < 2; h++) {
            const int row = wm * 32 + mt * 16 + lq + 8 * h;
            const float inv = 1.0f / (s[L_F + row] + s[L_F + 128 + row] +
                                      s[L_F + 256 + row] + s[L_F + 384 + row]);
            float* o = out + (size_t)(bTT + i0 + row) * DD + dc0 + wn * 64 + lr * 2;
#pragma unroll
            for (int nt = 0; nt < 8; nt++) {
                *(float2*)(o + nt * 8) = make_float2(acc[mt][nt][2 * h] * inv,
                                                     acc[mt][nt][2 * h + 1] * inv);
            }
        }
    }
}

extern "C" void kernel_launch(void* const* d_in, const int* in_sizes, int n_in,
                              void* d_out, int out_size) {
    const float* x = (const float*)d_in[0];   // [B,T,D] fp32
    const float* U = (const float*)d_in[1];   // [D,R]   fp32
    float* out = (float*)d_out;

    cudaFuncSetAttribute(yn_kernel, cudaFuncAttributeMaxDynamicSharedMemorySize,
                         K1_SMEM);
    yn_kernel<<<(BB * TT) / 64, 256, K1_SMEM>>>(x, U);

    cudaFuncSetAttribute(flash_kernel, cudaFuncAttributeMaxDynamicSharedMemorySize,
                         SMEM_TOTAL);
    dim3 grid(DD / DC, TT / BM, BB);
    flash_kernel<<<grid, 512, SMEM_TOTAL>>>(x, out);
}

// round 6
// speedup vs baseline: 5.1207x; 1.0256x over previous
#include <cuda_runtime.h>

typedef unsigned int u32;

#define BB 4
#define TT 2048
#define DD 1024
#define RR 32

#define BM 64
#define BN 32
#define DC 256
#define NT (TT / BN)

// scratch (no allocations allowed)
__device__ float g_y[BB * TT * RR];     // y = x @ U (tf32-rounded)
__device__ float g_n[BB * TT];          // ||y||^2
__device__ float g_xr[BB * TT * DD];    // tf32-rna-rounded copy of x

__device__ __forceinline__ u32 s2u(const void* p) {
    u32 a;
    asm("{ .reg .u64 t; cvta.to.shared.u64 t, %1; cvt.u32.u64 %0, t; }" : "=r"(a) : "l"(p));
    return a;
}
__device__ __forceinline__ void cp16(u32 dst, const void* src) {
    asm volatile("cp.async.cg.shared.global [%0], [%1], 16;" :: "r"(dst), "l"(src));
}
__device__ __forceinline__ u32 fu(float v) { return __float_as_uint(v); }
__device__ __forceinline__ float tf32f(float v) {
    u32 r;
    asm("cvt.rna.tf32.f32 %0, %1;" : "=r"(r) : "f"(v));
    return __uint_as_float(r);
}

// ---------------------------------------------------------------------------
// Kernel 1: y = x @ U (rounded), n = rowsum(y*y), g_xr = round(x).
// Block: 256 threads / 8 warps, 64 rows. Grid: 128. Double-buffered d-chunks.
// ---------------------------------------------------------------------------
#define K1_XF(q) ((q) * 8192)            // [64][128] floats
#define K1_UF(q) (16384 + (q) * 4608)    // [128][36] floats
#define K1_SMEM ((16384 + 2 * 4608) * 4) // 102400 B

__global__ __launch_bounds__(256, 1) void yn_kernel(const float* __restrict__ x,
                                                    const float* __restrict__ U) {
    extern __shared__ float s[];
    const u32 su = s2u(s);

    const int tid  = threadIdx.x;
    const int w    = tid >> 5;
    const int lane = tid & 31;
    const int row0 = blockIdx.x * 64;

    // prologue: chunk 0
    for (int idx = tid; idx < 2048; idx += 256) {
        int r_ = idx >> 5, u = idx & 31;
        cp16(su + K1_XF(0) * 4 + (r_ * 128 + u * 4) * 4,
             x + (size_t)(row0 + r_) * DD + u * 4);
    }
    for (int idx = tid; idx < 1024; idx += 256) {
        int d = idx >> 3, u = idx & 7;
        cp16(su + K1_UF(0) * 4 + (d * 36 + u * 4) * 4,
             U + (size_t)d * RR + u * 4);
    }
    asm volatile("cp.async.commit_group;" ::: "memory");

    float acc[8];
#pragma unroll
    for (int k = 0; k < 8; k++) acc[k] = 0.f;

    for (int c = 0; c < 8; c++) {
        const int q = c & 1;
        asm volatile("cp.async.wait_group 0;" ::: "memory");
        __syncthreads();

        if (c + 1 < 8) {
            const int d0n = (c + 1) * 128;
            for (int idx = tid; idx < 2048; idx += 256) {
                int r_ = idx >> 5, u = idx & 31;
                cp16(su + K1_XF(1 - q) * 4 + (r_ * 128 + u * 4) * 4,
                     x + (size_t)(row0 + r_) * DD + d0n + u * 4);
            }
            for (int idx = tid; idx < 1024; idx += 256) {
                int d = idx >> 3, u = idx & 7;
                cp16(su + K1_UF(1 - q) * 4 + ((d * 36 + u * 4)) * 4,
                     U + (size_t)(d0n + d) * RR + u * 4);
            }
            asm volatile("cp.async.commit_group;" ::: "memory");
        }

        const float* sX = s + K1_XF(q);
        const float* sU = s + K1_UF(q);
#pragma unroll
        for (int dd4 = 0; dd4 < 32; dd4++) {
            float u0 = sU[(dd4 * 4 + 0) * 36 + lane];
            float u1 = sU[(dd4 * 4 + 1) * 36 + lane];
            float u2 = sU[(dd4 * 4 + 2) * 36 + lane];
            float u3 = sU[(dd4 * 4 + 3) * 36 + lane];
#pragma unroll
            for (int k = 0; k < 8; k++) {
                const float4 xv = *(const float4*)&sX[(w * 8 + k) * 128 + dd4 * 4];
                acc[k] = fmaf(xv.x, u0, acc[k]);
                acc[k] = fmaf(xv.y, u1, acc[k]);
                acc[k] = fmaf(xv.z, u2, acc[k]);
                acc[k] = fmaf(xv.w, u3, acc[k]);
            }
        }

        // write rounded x chunk to g_xr
        const int d0 = c * 128;
        for (int idx = tid; idx < 2048; idx += 256) {
            int r_ = idx >> 5, u = idx & 31;
            float4 xv = *(const float4*)&sX[r_ * 128 + u * 4];
            xv.x = tf32f(xv.x); xv.y = tf32f(xv.y);
            xv.z = tf32f(xv.z); xv.w = tf32f(xv.w);
            *(float4*)&g_xr[(size_t)(row0 + r_) * DD + d0 + u * 4] = xv;
        }
    }

#pragma unroll
    for (int k = 0; k < 8; k++) {
        int rg = row0 + w * 8 + k;
        float ar = tf32f(acc[k]);
        g_y[(size_t)rg * RR + lane] = ar;
        float v = ar * ar;
#pragma unroll
        for (int off = 16; off; off >>= 1)
            v += __shfl_xor_sync(0xffffffffu, v, off);
        if (lane == 0) g_n[rg] = v;
    }
}

// ---------------------------------------------------------------------------
// Kernel 2: flash attention via mma.sync tf32 (static max = n_i, no rescale)
// 8 warps as 2 wm x 4 wn; warp tile 32m x 64n; 2 CTAs/SM.
// ---------------------------------------------------------------------------
#define YI_F 0                         // [64][36]
#define P_F  2304                      // [64][36]
#define YJ_F(q) (4608 + (q) * 1152)    // [32][36] x2
#define NJ_F(q) (6912 + (q) * 32)      // [32] x2
#define L_F  0                         // [4][64] (reuses YI in epilogue)
#define X_F(q) (6976 + (q) * 8448)     // [32][264] x2
#define SMEM_TOTAL ((6976 + 2 * 8448) * 4)   // 95488 B

#define YSTR 36
#define XSTR 264

__device__ __forceinline__ void mma8(float* d, const u32* a, u32 b0, u32 b1,
                                     const float* c) {
    asm volatile(
        "mma.sync.aligned.m16n8k8.row.col.f32.tf32.tf32.f32 "
        "{%0,%1,%2,%3}, {%4,%5,%6,%7}, {%8,%9}, {%10,%11,%12,%13};"
        : "=f"(d[0]), "=f"(d[1]), "=f"(d[2]), "=f"(d[3])
        : "r"(a[0]), "r"(a[1]), "r"(a[2]), "r"(a[3]), "r"(b0), "r"(b1),
          "f"(c[0]), "f"(c[1]), "f"(c[2]), "f"(c[3]));
}

__global__ __launch_bounds__(256, 2) void flash_kernel(float* __restrict__ out) {
    extern __shared__ float s[];
    const u32 su = s2u(s);

    const int tid  = threadIdx.x;
    const int w    = tid >> 5;
    const int lane = tid & 31;
    const int wm   = w >> 2;        // 0..1 : 32 query rows each
    const int wn   = w & 3;         // 0..3 : 64 d-cols (MMA2) / 8 s-cols (MMA1)
    const int lq   = lane >> 2;     // 0..7
    const int lr   = lane & 3;      // 0..3

    const int b   = blockIdx.z;
    const int i0  = blockIdx.y * BM;
    const int dc0 = blockIdx.x * DC;
    const int bTT = b * TT;

    // ---- prologue: Yi + tile 0 ----
    for (int idx = tid; idx < 512; idx += 256) {
        int r_ = idx >> 3, u = idx & 7;
        cp16(su + (YI_F + r_ * YSTR) * 4 + u * 16,
             g_y + (size_t)(bTT + i0 + r_) * RR + u * 4);
    }
    for (int idx = tid; idx < 2048; idx += 256) {
        int r_ = idx >> 6, u = idx & 63;
        cp16(su + X_F(0) * 4 + r_ * (XSTR * 4) + u * 16,
             g_xr + (size_t)(bTT + r_) * DD + dc0 + u * 4);
    }
    if (tid < 256) {
        int r_ = tid >> 3, u = tid & 7;
        cp16(su + (YJ_F(0) + r_ * YSTR) * 4 + u * 16,
             g_y + (size_t)(bTT + r_) * RR + u * 4);
    }
    if (tid < 8)
        cp16(su + NJ_F(0) * 4 + tid * 16, g_n + bTT + tid * 4);
    asm volatile("cp.async.commit_group;" ::: "memory");

    float ni[2][2];
#pragma unroll
    for (int mt = 0; mt < 2; mt++) {
        ni[mt][0] = g_n[bTT + i0 + wm * 32 + mt * 16 + lq];
        ni[mt][1] = g_n[bTT + i0 + wm * 32 + mt * 16 + lq + 8];
    }

    float acc[2][8][4];
#pragma unroll
    for (int mt = 0; mt < 2; mt++)
#pragma unroll
        for (int nt = 0; nt < 8; nt++)
#pragma unroll
            for (int c = 0; c < 4; c++) acc[mt][nt][c] = 0.f;
    float lsum[2][2] = {{0.f, 0.f}, {0.f, 0.f}};

    for (int t = 0; t < NT; t++) {
        const int q = t & 1;

        asm volatile("cp.async.wait_group 0;" ::: "memory");
        __syncthreads();   // tile t visible; prior readers of buf 1-q done

        if (t + 1 < NT) {  // prefetch t+1 into buf 1-q
            const int j0n = (t + 1) * BN;
            for (int idx = tid; idx < 2048; idx += 256) {
                int r_ = idx >> 6, u = idx & 63;
                cp16(su + X_F(1 - q) * 4 + r_ * (XSTR * 4) + u * 16,
                     g_xr + (size_t)(bTT + j0n + r_) * DD + dc0 + u * 4);
            }
            if (tid < 256) {
                int r_ = tid >> 3, u = tid & 7;
                cp16(su + (YJ_F(1 - q) + r_ * YSTR) * 4 + u * 16,
                     g_y + (size_t)(bTT + j0n + r_) * RR + u * 4);
            }
            if (tid < 8)
                cp16(su + NJ_F(1 - q) * 4 + tid * 16, g_n + bTT + j0n + tid * 4);
            asm volatile("cp.async.commit_group;" ::: "memory");
        }

        // ---- MMA1: S[32m x 8n] per warp ----
        float S[2][4];
        {
            u32 aY[4];
            const int yjb = YJ_F(q) + (wn * 8 + lq) * YSTR + lr;
#pragma unroll
            for (int mt = 0; mt < 2; mt++)
#pragma unroll
                for (int c = 0; c < 4; c++) S[mt][c] = 0.f;
#pragma unroll
            for (int kt = 0; kt < 4; kt++) {
                u32 b0 = fu(s[yjb + kt * 8]);
                u32 b1 = fu(s[yjb + kt * 8 + 4]);
#pragma unroll
                for (int mt = 0; mt < 2; mt++) {
                    const int yib = YI_F + (wm * 32 + mt * 16 + lq) * YSTR + kt * 8 + lr;
                    aY[0] = fu(s[yib]);
                    aY[1] = fu(s[yib + 8 * YSTR]);
                    aY[2] = fu(s[yib + 4]);
                    aY[3] = fu(s[yib + 8 * YSTR + 4]);
                    mma8(S[mt], aY, b0, b1, S[mt]);
                }
            }
        }

        // ---- softmax: p = exp(2S - ni - nj); store to sP ----
        {
            const float2 nj = *(const float2*)&s[NJ_F(q) + wn * 8 + lr * 2];
#pragma unroll
            for (int mt = 0; mt < 2; mt++) {
                float p0 = __expf(fmaf(S[mt][0], 2.f, -ni[mt][0] - nj.x));
                float p1 = __expf(fmaf(S[mt][1], 2.f, -ni[mt][0] - nj.y));
                float p2 = __expf(fmaf(S[mt][2], 2.f, -ni[mt][1] - nj.x));
                float p3 = __expf(fmaf(S[mt][3], 2.f, -ni[mt][1] - nj.y));
                lsum[mt][0] += p0 + p1;
                lsum[mt][1] += p2 + p3;
                const int pb = P_F + (wm * 32 + mt * 16 + lq) * YSTR + wn * 8 + lr * 2;
                *(float2*)&s[pb]            = make_float2(p0, p1);
                *(float2*)&s[pb + 8 * YSTR] = make_float2(p2, p3);
            }
        }
        __syncthreads();   // sP visible

        // ---- MMA2: acc[32m x 64n] += P[32m x 32k] @ X[32k x 64n] ----
        u32 aP[2][4][4];
#pragma unroll
        for (int mt = 0; mt < 2; mt++) {
            const int pab = P_F + (wm * 32 + mt * 16 + lq) * YSTR + lr;
#pragma unroll
            for (int kt = 0; kt < 4; kt++) {
                aP[mt][kt][0] = fu(s[pab + kt * 8]);
                aP[mt][kt][1] = fu(s[pab + kt * 8 + 8 * YSTR]);
                aP[mt][kt][2] = fu(s[pab + kt * 8 + 4]);
                aP[mt][kt][3] = fu(s[pab + kt * 8 + 8 * YSTR + 4]);
            }
        }
        const int xb = X_F(q) + lr * XSTR + wn * 64 + lq;
#pragma unroll
        for (int nt = 0; nt < 8; nt++) {
#pragma unroll
            for (int kt = 0; kt < 4; kt++) {
                u32 b0 = fu(s[xb + kt * 8 * XSTR + nt * 8]);
                u32 b1 = fu(s[xb + (kt * 8 + 4) * XSTR + nt * 8]);
                mma8(acc[0][nt], aP[0][kt], b0, b1, acc[0][nt]);
                mma8(acc[1][nt], aP[1][kt], b0, b1, acc[1][nt]);
            }
        }
    }

    // ---- epilogue: reduce l across quad + 4 wn groups, normalize, store ----
    __syncthreads();   // done with Yi region; reuse as L
#pragma unroll
    for (int mt = 0; mt < 2; mt++)
#pragma unroll
        for (int h = 0; h < 2; h++) {
            float v = lsum[mt][h];
            v += __shfl_xor_sync(0xffffffffu, v, 1);
            v += __shfl_xor_sync(0xffffffffu, v, 2);
            if (lr == 0)
                s[L_F + wn * 64 + wm * 32 + mt * 16 + lq + 8 * h] = v;
        }
    __syncthreads();

#pragma unroll
    for (int mt = 0; mt < 2; mt++) {
#pragma unroll
        for (int h = 0; h < 2; h++) {
            const int row = wm * 32 + mt * 16 + lq + 8 * h;
            const float inv = 1.0f / (s[L_F + row] + s[L_F + 64 + row] +
                                      s[L_F + 128 + row] + s[L_F + 192 + row]);
            float* o = out + (size_t)(bTT + i0 + row) * DD + dc0 + wn * 64 + lr * 2;
#pragma unroll
            for (int nt = 0; nt < 8; nt++) {
                *(float2*)(o + nt * 8) = make_float2(acc[mt][nt][2 * h] * inv,
                                                     acc[mt][nt][2 * h + 1] * inv);
            }
        }
    }
}

extern "C" void kernel_launch(void* const* d_in, const int* in_sizes, int n_in,
                              void* d_out, int out_size) {
    const float* x = (const float*)d_in[0];   // [B,T,D] fp32
    const float* U = (const float*)d_in[1];   // [D,R]   fp32
    float* out = (float*)d_out;

    cudaFuncSetAttribute(yn_kernel, cudaFuncAttributeMaxDynamicSharedMemorySize,
                         K1_SMEM);
    yn_kernel<<<(BB * TT) / 64, 256, K1_SMEM>>>(x, U);

    cudaFuncSetAttribute(flash_kernel, cudaFuncAttributeMaxDynamicSharedMemorySize,
                         SMEM_TOTAL);
    dim3 grid(DD / DC, TT / BM, BB);
    flash_kernel<<<grid, 256, SMEM_TOTAL>>>(out);
}